// round 1
// baseline (speedup 1.0000x reference)
#include <cuda_runtime.h>
#include <cuda_bf16.h>

// TactileSpikeEncoder: bit-exact JAX threefry2x32 (partitionable mode) spike encoder.
// Pipeline: k_init (per-t keys) -> k_thresh (integer spike thresholds)
//        -> k_rng (all RNG once, packed spike-candidate bits + potOcc OR)
//        -> k_scan (refractory recurrence, 256 neurons x 100 steps)
//        -> k_out (gate & expand to float32 output [B,F,N,T])

#define TT      100
#define NNEUR   256
#define TOTAL   524288   // 32*64*256 elements per timestep
#define NBLK    2048     // TOTAL/256

__device__ unsigned g_keys[TT * 3];         // k0,k1,k2(=k0^k1^0x1BD11BDA) per t
__device__ unsigned g_thresh[TOTAL];        // integer spike thresholds
__device__ uint4    g_sbits[TOTAL];         // 100-bit candidate-spike mask per element (8 MB)
__device__ unsigned g_potOcc[NNEUR * 4];    // OR over (b,f) of candidate bits, per neuron
__device__ unsigned g_gate[NNEUR * 4];      // active (ref==0) mask per neuron

__device__ __forceinline__ void tf_g4(unsigned &x0, unsigned &x1,
                                      int r0, int r1, int r2, int r3) {
    x0 += x1; x1 = __funnelshift_l(x1, x1, r0); x1 ^= x0;
    x0 += x1; x1 = __funnelshift_l(x1, x1, r1); x1 ^= x0;
    x0 += x1; x1 = __funnelshift_l(x1, x1, r2); x1 ^= x0;
    x0 += x1; x1 = __funnelshift_l(x1, x1, r3); x1 ^= x0;
}

// Threefry-2x32, 20 rounds, exactly as in jax._src.prng.threefry2x32.
__device__ __forceinline__ void tf2x32(unsigned k0, unsigned k1, unsigned k2,
                                       unsigned &x0, unsigned &x1) {
    x0 += k0; x1 += k1;
    tf_g4(x0, x1, 13, 15, 26, 6);
    x0 += k1; x1 += k2 + 1u;
    tf_g4(x0, x1, 17, 29, 16, 24);
    x0 += k2; x1 += k0 + 2u;
    tf_g4(x0, x1, 13, 15, 26, 6);
    x0 += k0; x1 += k1 + 3u;
    tf_g4(x0, x1, 17, 29, 16, 24);
    x0 += k1; x1 += k2 + 4u;
    tf_g4(x0, x1, 13, 15, 26, 6);
    x0 += k2; x1 += k0 + 5u;
}

// Per-timestep keys: key_t = threefry(base_key=(0,seed); count=(0,t))  [fold_in].
// Also zeroes potOcc accumulator (atomicOr is idempotent across graph replays,
// but re-zeroing keeps every replay identical from scratch).
__global__ void k_init(const int* __restrict__ seedp) {
    int t = threadIdx.x;
    unsigned s = (unsigned)seedp[0];
    if (t < TT) {
        unsigned k0 = 0u, k1 = s;
        unsigned k2 = k0 ^ k1 ^ 0x1BD11BDAu;
        unsigned x0 = 0u, x1 = (unsigned)t;
        tf2x32(k0, k1, k2, x0, x1);
        g_keys[3 * t + 0] = x0;
        g_keys[3 * t + 1] = x1;
        g_keys[3 * t + 2] = x0 ^ x1 ^ 0x1BD11BDAu;
    }
    for (int q = t; q < NNEUR * 4; q += blockDim.x) g_potOcc[q] = 0u;
}

// Integer threshold: spike <=> (bits>>9) < ceil(p * 2^23).
// p computed with the exact reference op order; mult by 2^23 is exact.
__global__ void k_thresh(const float* __restrict__ x,
                         const float* __restrict__ centers,
                         const float* __restrict__ widths,
                         const float* __restrict__ adapt) {
    unsigned i = blockIdx.x * 256u + threadIdx.x;
    int n = (int)(i & 255u);
    float xv = x[i >> 8];
    float c = centers[n];
    float w = widths[n];
    float d = xv - c;
    float num = -(d * d);
    float den = (2.0f * w) * w;
    float resp = expf(num / den);
    resp = resp * adapt[n];          // reference applies initial adaptation once
    float p = resp * 0.1f;           // SPIKE_RATE/1000
    g_thresh[i] = (unsigned)ceilf(p * 8388608.0f);
}

// The hot kernel: 52.4M threefry blocks. Thread i covers element i for all 100 t.
// Partitionable mode: counter = (0, i), bits = y0 ^ y1.
__global__ void __launch_bounds__(256) k_rng() {
    __shared__ unsigned sk[TT * 3];
    int tid = threadIdx.x;
    for (int q = tid; q < TT * 3; q += 256) sk[q] = g_keys[q];
    __syncthreads();

    unsigned i = blockIdx.x * 256u + tid;
    unsigned T = g_thresh[i];

    unsigned mask[4];
#pragma unroll
    for (int w = 0; w < 4; w++) {
        unsigned mw = 0u;
        const int nb = (w < 3) ? 32 : 4;
#pragma unroll 4
        for (int b = 0; b < nb; b++) {
            int t = w * 32 + b;
            unsigned k0 = sk[3 * t], k1 = sk[3 * t + 1], k2 = sk[3 * t + 2];
            unsigned x0 = 0u, x1 = i;
            tf2x32(k0, k1, k2, x0, x1);
            unsigned bits = x0 ^ x1;
            if ((bits >> 9) < T) mw |= (1u << b);
        }
        mask[w] = mw;
    }

    g_sbits[i] = make_uint4(mask[0], mask[1], mask[2], mask[3]);

    int n = (int)(i & 255u);
    if (mask[0]) atomicOr(&g_potOcc[n * 4 + 0], mask[0]);
    if (mask[1]) atomicOr(&g_potOcc[n * 4 + 1], mask[1]);
    if (mask[2]) atomicOr(&g_potOcc[n * 4 + 2], mask[2]);
    if (mask[3]) atomicOr(&g_potOcc[n * 4 + 3], mask[3]);
}

// Refractory recurrence per neuron. active[t] = (ref==0); occurred = candidate & active;
// ref = max(ref-1,0) + 2*occurred.
__global__ void k_scan(const float* __restrict__ refr) {
    int n = threadIdx.x;
    unsigned p0 = g_potOcc[n * 4 + 0], p1 = g_potOcc[n * 4 + 1];
    unsigned p2 = g_potOcc[n * 4 + 2], p3 = g_potOcc[n * 4 + 3];
    float ref = refr[n];
    unsigned g0 = 0u, g1 = 0u, g2 = 0u, g3 = 0u;
#pragma unroll
    for (int t = 0; t < TT; t++) {
        unsigned pw = (t < 32) ? p0 : ((t < 64) ? p1 : ((t < 96) ? p2 : p3));
        bool active = (ref == 0.0f);
        unsigned bit = (pw >> (t & 31)) & 1u;
        unsigned occ = active ? bit : 0u;
        if (active) {
            if (t < 32)      g0 |= (1u << t);
            else if (t < 64) g1 |= (1u << (t - 32));
            else if (t < 96) g2 |= (1u << (t - 64));
            else             g3 |= (1u << (t - 96));
        }
        ref = fmaxf(ref - 1.0f, 0.0f) + 2.0f * (float)occ;
    }
    g_gate[n * 4 + 0] = g0; g_gate[n * 4 + 1] = g1;
    g_gate[n * 4 + 2] = g2; g_gate[n * 4 + 3] = g3;
}

// Expand gated bitmasks to float32 output. Thread i writes its contiguous 400 B run.
__global__ void k_out(float* __restrict__ out) {
    unsigned i = blockIdx.x * 256u + threadIdx.x;
    uint4 s = g_sbits[i];
    int n = (int)(i & 255u);
    unsigned w0 = s.x & g_gate[n * 4 + 0];
    unsigned w1 = s.y & g_gate[n * 4 + 1];
    unsigned w2 = s.z & g_gate[n * 4 + 2];
    unsigned w3 = s.w & g_gate[n * 4 + 3];

    float4* o = reinterpret_cast<float4*>(out + (size_t)i * TT);
#pragma unroll
    for (int q = 0; q < 25; q++) {
        int t0 = q * 4;
        unsigned word = (t0 < 32) ? w0 : ((t0 < 64) ? w1 : ((t0 < 96) ? w2 : w3));
        int sh = t0 & 31;
        float4 v;
        v.x = ((word >> (sh + 0)) & 1u) ? 1.0f : 0.0f;
        v.y = ((word >> (sh + 1)) & 1u) ? 1.0f : 0.0f;
        v.z = ((word >> (sh + 2)) & 1u) ? 1.0f : 0.0f;
        v.w = ((word >> (sh + 3)) & 1u) ? 1.0f : 0.0f;
        o[q] = v;
    }
}

extern "C" void kernel_launch(void* const* d_in, const int* in_sizes, int n_in,
                              void* d_out, int out_size) {
    (void)in_sizes; (void)n_in; (void)out_size;
    const float* x       = (const float*)d_in[0];
    const float* centers = (const float*)d_in[1];
    const float* widths  = (const float*)d_in[2];
    const float* adapt   = (const float*)d_in[3];
    const float* refr    = (const float*)d_in[4];
    const int*   seed    = (const int*)d_in[5];
    float* out = (float*)d_out;

    k_init  <<<1, 128>>>(seed);
    k_thresh<<<NBLK, 256>>>(x, centers, widths, adapt);
    k_rng   <<<NBLK, 256>>>();
    k_scan  <<<1, NNEUR>>>(refr);
    k_out   <<<NBLK, 256>>>(out);
}